// round 8
// baseline (speedup 1.0000x reference)
#include <cuda_runtime.h>
#include <cuda_bf16.h>

#define SEQ_LEN 512
#define BATCH   256
#define CAUSES  64
#define STATES  512
#define OUT_DIM 256
#define RPC     4
#define NCTA    (BATCH / RPC)
#define NT      512
#define HALFT   256

#define ALPHA_X 0.1f
#define ALPHA_H 0.1f

typedef unsigned long long u64;

// ---------------- packed weight scratch (device globals: allocation-free) ----
__device__ float g_wrP[STATES/2 * STATES * 2];            // 262144
__device__ float g_wcB[CAUSES/2 * STATES * 2];            // 32768
__device__ float g_woC[STATES/4 * OUT_DIM * 4];           // 131072
__device__ float g_woD[OUT_DIM/2 * STATES * 2];           // 131072
__device__ float g_wcE[STATES/2 * CAUSES * 2];            // 32768

// ---------------- packed f32x2 helpers (PTX; ptxas won't auto-fuse) ----
__device__ __forceinline__ u64 dup2(float s) {
    u64 r; asm("mov.b64 %0, {%1, %1};" : "=l"(r) : "f"(s)); return r;
}
__device__ __forceinline__ u64 pack2(float a, float b) {
    u64 r; asm("mov.b64 %0, {%1, %2};" : "=l"(r) : "f"(a), "f"(b)); return r;
}
__device__ __forceinline__ void fma2(u64& d, u64 a, u64 b) {
    asm("fma.rn.f32x2 %0, %1, %2, %3;" : "=l"(d) : "l"(a), "l"(b), "l"(d));
}
__device__ __forceinline__ void add2(u64& d, u64 a, u64 b) {
    asm("add.rn.f32x2 %0, %1, %2;" : "=l"(d) : "l"(a), "l"(b));
}
__device__ __forceinline__ void unpack2(u64 v, float& lo, float& hi) {
    asm("mov.b64 {%0, %1}, %2;" : "=f"(lo), "=f"(hi) : "l"(v));
}

// ---------------- prologue pack kernels ----------
__global__ void pack_wrB(const float* __restrict__ w) {        // w_r [512][512]
    int idx = blockIdx.x * 256 + threadIdx.x;
    int k2 = idx >> 10, rem = idx & 1023;
    int jp = rem >> 2, c = rem & 3;
    int j = jp * 2 + (c & 1), k = k2 * 2 + (c >> 1);
    g_wrP[idx] = w[j * STATES + k];
}
__global__ void pack_wcB(const float* __restrict__ w) {        // w_c [512][64]
    int idx = blockIdx.x * 256 + threadIdx.x;
    int m2 = idx >> 10, rem = idx & 1023;
    int jp = rem >> 2, c = rem & 3;
    int j = jp * 2 + (c & 1), m = m2 * 2 + (c >> 1);
    g_wcB[idx] = w[j * CAUSES + m];
}
__global__ void pack_woC(const float* __restrict__ w) {        // w_o [256][512]
    int idx = blockIdx.x * 256 + threadIdx.x;
    int j4 = idx >> 10, rem = idx & 1023;
    int o = rem >> 2, jj = rem & 3;
    g_woC[idx] = w[o * STATES + j4 * 4 + jj];
}
__global__ void pack_woD(const float* __restrict__ w) {        // w_o [256][512]
    int idx = blockIdx.x * 256 + threadIdx.x;
    int o2 = idx >> 10, rem = idx & 1023;
    int jp = rem >> 2, c = rem & 3;
    int j = jp * 2 + (c & 1), o = o2 * 2 + (c >> 1);
    g_woD[idx] = w[o * STATES + j];
}
__global__ void pack_wcE(const float* __restrict__ w) {        // w_c [512][64]
    int idx = blockIdx.x * 256 + threadIdx.x;
    int j2 = idx >> 7, rem = idx & 127;
    int m = rem >> 1, jj = rem & 1;
    g_wcE[idx] = w[(j2 * 2 + jj) * CAUSES + m];
}

// ---------------- main persistent recurrence kernel (split-K, 16 warps) ----
__global__ __launch_bounds__(NT, 1)
void pc_rnn_kernel(const float* __restrict__ x,
                   const float* __restrict__ c_init,
                   const float* __restrict__ h_init,
                   const float* __restrict__ b_o,
                   const float* __restrict__ b_r,
                   float* __restrict__ out)
{
    __shared__ u64 s_th2 [STATES  * RPC];     // tanh(h_post) dup'd  [k][r]   16KB
    __shared__ u64 s_tp2 [STATES  * 2];       // tanh(h_prior) pairs [j][rp]   8KB
    __shared__ u64 s_err2[OUT_DIM * RPC];     // error dup'd         [o][r]    8KB
    __shared__ u64 s_eh2 [(STATES/2) * RPC];  // error_h j-pairs     [j2][r]   8KB
    __shared__ u64 s_c2  [CAUSES  * RPC];     // c dup'd             [m][r]    2KB
    __shared__ u64 s_part[HALFT * 4];         // partial exchange              8KB

    const int tid  = threadIdx.x;
    const int lid  = tid & (HALFT - 1);
    const int uppr = tid >> 8;                // 0 = finalizer half, 1 = helper half
    const int b0   = blockIdx.x * RPC;
    const int j0   = lid * 2;

    const float4* __restrict__ wrB = (const float4*)g_wrP;
    const float4* __restrict__ wcB = (const float4*)g_wcB;
    const float4* __restrict__ woC = (const float4*)g_woC;
    const float4* __restrict__ woD = (const float4*)g_woD;
    const u64*    __restrict__ wcE = (const u64*)g_wcE;

    float h0[RPC], h1[RPC], hp0[RPC], hp1[RPC], tp0[RPC], tp1[RPC];
    float rb0 = 0.f, rb1 = 0.f, rbo = 0.f, creg = 0.f;
    const int cm = lid & 63, cr = lid >> 6;

    if (!uppr) {
#pragma unroll
        for (int r = 0; r < RPC; ++r) {
            h0[r] = h_init[(size_t)(b0 + r) * STATES + j0];
            h1[r] = h_init[(size_t)(b0 + r) * STATES + j0 + 1];
            s_th2[(j0)     * RPC + r] = dup2(tanhf(h0[r]));
            s_th2[(j0 + 1) * RPC + r] = dup2(tanhf(h1[r]));
        }
        rb0 = b_r[j0]; rb1 = b_r[j0 + 1];
        rbo = b_o[lid];
        creg = c_init[(size_t)(b0 + cr) * CAUSES + cm];
        s_c2[cm * RPC + cr] = dup2(creg);
    }
    __syncthreads();

    for (int t = 0; t < SEQ_LEN; ++t) {
        // prefetch x_t (finalizer half only; hidden behind phase B)
        float xr[RPC];
        if (!uppr) {
#pragma unroll
            for (int r = 0; r < RPC; ++r)
                xr[r] = x[((size_t)t * BATCH + b0 + r) * OUT_DIM + lid];
        }

        // ---------- Phase B partial: th@WrT + c@WcT over this half's k range ----------
        u64 acc[RPC];
#pragma unroll
        for (int r = 0; r < RPC; ++r) acc[r] = 0ULL;
        {
            const int bk2 = uppr * 128;
            // depth-2, batch-2 software pipeline on the weight stream
            float4 pa0 = wrB[(bk2 + 0) * 256 + lid];
            float4 pa1 = wrB[(bk2 + 1) * 256 + lid];
            float4 pb0 = wrB[(bk2 + 2) * 256 + lid];
            float4 pb1 = wrB[(bk2 + 3) * 256 + lid];
#pragma unroll 2
            for (int k2i = 0; k2i < 128; k2i += 2) {
                float4 c0 = pa0, c1 = pa1;
                pa0 = pb0; pa1 = pb1;
                int nx = k2i + 4; nx = (nx > 126) ? 124 : nx;
                pb0 = wrB[(bk2 + nx)     * 256 + lid];
                pb1 = wrB[(bk2 + nx + 1) * 256 + lid];
                {
                    const int k = (bk2 + k2i) * 2;
                    ulonglong2 ta = *(const ulonglong2*)&s_th2[k * RPC];
                    ulonglong2 tb = *(const ulonglong2*)&s_th2[k * RPC + 2];
                    ulonglong2 tc = *(const ulonglong2*)&s_th2[k * RPC + 4];
                    ulonglong2 td = *(const ulonglong2*)&s_th2[k * RPC + 6];
                    u64 wlo = pack2(c0.x, c0.y), whi = pack2(c0.z, c0.w);
                    fma2(acc[0], ta.x, wlo);
                    fma2(acc[1], ta.y, wlo);
                    fma2(acc[2], tb.x, wlo);
                    fma2(acc[3], tb.y, wlo);
                    fma2(acc[0], tc.x, whi);
                    fma2(acc[1], tc.y, whi);
                    fma2(acc[2], td.x, whi);
                    fma2(acc[3], td.y, whi);
                }
                {
                    const int k = (bk2 + k2i + 1) * 2;
                    ulonglong2 ta = *(const ulonglong2*)&s_th2[k * RPC];
                    ulonglong2 tb = *(const ulonglong2*)&s_th2[k * RPC + 2];
                    ulonglong2 tc = *(const ulonglong2*)&s_th2[k * RPC + 4];
                    ulonglong2 td = *(const ulonglong2*)&s_th2[k * RPC + 6];
                    u64 wlo = pack2(c1.x, c1.y), whi = pack2(c1.z, c1.w);
                    fma2(acc[0], ta.x, wlo);
                    fma2(acc[1], ta.y, wlo);
                    fma2(acc[2], tb.x, wlo);
                    fma2(acc[3], tb.y, wlo);
                    fma2(acc[0], tc.x, whi);
                    fma2(acc[1], tc.y, whi);
                    fma2(acc[2], td.x, whi);
                    fma2(acc[3], td.y, whi);
                }
            }
            const int bm2 = uppr * 16;
#pragma unroll 8
            for (int m2i = 0; m2i < 16; ++m2i) {
                const int m2 = bm2 + m2i;
                float4 w = wcB[m2 * 256 + lid];
                const int m = m2 * 2;
                ulonglong2 ca_ = *(const ulonglong2*)&s_c2[m * RPC];
                ulonglong2 cb_ = *(const ulonglong2*)&s_c2[m * RPC + 2];
                ulonglong2 cc_ = *(const ulonglong2*)&s_c2[m * RPC + 4];
                ulonglong2 cd_ = *(const ulonglong2*)&s_c2[m * RPC + 6];
                u64 wlo = pack2(w.x, w.y), whi = pack2(w.z, w.w);
                fma2(acc[0], ca_.x, wlo);
                fma2(acc[1], ca_.y, wlo);
                fma2(acc[2], cb_.x, wlo);
                fma2(acc[3], cb_.y, wlo);
                fma2(acc[0], cc_.x, whi);
                fma2(acc[1], cc_.y, whi);
                fma2(acc[2], cd_.x, whi);
                fma2(acc[3], cd_.y, whi);
            }
        }
        if (uppr) {
#pragma unroll
            for (int r = 0; r < RPC; ++r) s_part[lid * 4 + r] = acc[r];
        }
        __syncthreads();

        // ---------- Phase B finalize: h_prior, tanh(h_prior) ----------
        if (!uppr) {
#pragma unroll
            for (int r = 0; r < RPC; ++r) {
                float a0, a1, p0, p1;
                unpack2(acc[r], a0, a1);
                unpack2(s_part[lid * 4 + r], p0, p1);
                a0 += p0; a1 += p1;
                hp0[r] = 0.9f * h0[r] + 0.1f * (a0 + rb0);
                hp1[r] = 0.9f * h1[r] + 0.1f * (a1 + rb1);
                tp0[r] = tanhf(hp0[r]);
                tp1[r] = tanhf(hp1[r]);
            }
            ulonglong2 v0, v1;
            v0.x = pack2(tp0[0], tp0[1]); v0.y = pack2(tp0[2], tp0[3]);
            v1.x = pack2(tp1[0], tp1[1]); v1.y = pack2(tp1[2], tp1[3]);
            *(ulonglong2*)&s_tp2[j0 * 2]     = v0;
            *(ulonglong2*)&s_tp2[j0 * 2 + 2] = v1;
        }
        __syncthreads();

        // ---------- Phase C partial: tp@WoT over this half's j range (o = lid) ----------
        {
            u64 e01 = 0ULL, e23 = 0ULL;
            const int bj4 = uppr * 64;
            float4 pa = woC[(bj4 + 0) * 256 + lid];
            float4 pb = woC[(bj4 + 1) * 256 + lid];
            float4 pc_ = woC[(bj4 + 2) * 256 + lid];
            float4 pd = woC[(bj4 + 3) * 256 + lid];
#pragma unroll 2
            for (int j4i = 0; j4i < 64; j4i += 2) {
                float4 c0 = pa, c1 = pb;
                pa = pc_; pb = pd;
                int nx = j4i + 4; nx = (nx > 62) ? 60 : nx;
                pc_ = woC[(bj4 + nx)     * 256 + lid];
                pd  = woC[(bj4 + nx + 1) * 256 + lid];
                {
                    const int j4 = bj4 + j4i;
                    ulonglong2 p0 = *(const ulonglong2*)&s_tp2[(j4 * 4 + 0) * 2];
                    ulonglong2 p1 = *(const ulonglong2*)&s_tp2[(j4 * 4 + 1) * 2];
                    ulonglong2 p2 = *(const ulonglong2*)&s_tp2[(j4 * 4 + 2) * 2];
                    ulonglong2 p3 = *(const ulonglong2*)&s_tp2[(j4 * 4 + 3) * 2];
                    u64 w0 = dup2(c0.x), w1 = dup2(c0.y), w2 = dup2(c0.z), w3 = dup2(c0.w);
                    fma2(e01, p0.x, w0); fma2(e23, p0.y, w0);
                    fma2(e01, p1.x, w1); fma2(e23, p1.y, w1);
                    fma2(e01, p2.x, w2); fma2(e23, p2.y, w2);
                    fma2(e01, p3.x, w3); fma2(e23, p3.y, w3);
                }
                {
                    const int j4 = bj4 + j4i + 1;
                    ulonglong2 p0 = *(const ulonglong2*)&s_tp2[(j4 * 4 + 0) * 2];
                    ulonglong2 p1 = *(const ulonglong2*)&s_tp2[(j4 * 4 + 1) * 2];
                    ulonglong2 p2 = *(const ulonglong2*)&s_tp2[(j4 * 4 + 2) * 2];
                    ulonglong2 p3 = *(const ulonglong2*)&s_tp2[(j4 * 4 + 3) * 2];
                    u64 w0 = dup2(c1.x), w1 = dup2(c1.y), w2 = dup2(c1.z), w3 = dup2(c1.w);
                    fma2(e01, p0.x, w0); fma2(e23, p0.y, w0);
                    fma2(e01, p1.x, w1); fma2(e23, p1.y, w1);
                    fma2(e01, p2.x, w2); fma2(e23, p2.y, w2);
                    fma2(e01, p3.x, w3); fma2(e23, p3.y, w3);
                }
            }
            if (uppr) {
                s_part[lid * 4]     = e01;
                s_part[lid * 4 + 1] = e23;
            } else {
                acc[0] = e01; acc[1] = e23;
            }
        }
        __syncthreads();

        // ---------- Phase C finalize: err = pred - x_t; out + s_err2 ----------
        if (!uppr) {
            float q0, q1, q2, q3, u0, u1, u2, u3;
            unpack2(acc[0], q0, q1); unpack2(acc[1], q2, q3);
            unpack2(s_part[lid * 4], u0, u1); unpack2(s_part[lid * 4 + 1], u2, u3);
            float er0 = (q0 + u0 + rbo) - xr[0];
            float er1 = (q1 + u1 + rbo) - xr[1];
            float er2 = (q2 + u2 + rbo) - xr[2];
            float er3 = (q3 + u3 + rbo) - xr[3];
            size_t ob = ((size_t)t * BATCH + b0) * OUT_DIM + lid;
            out[ob]               = er0;
            out[ob + OUT_DIM]     = er1;
            out[ob + 2 * OUT_DIM] = er2;
            out[ob + 3 * OUT_DIM] = er3;
            ulonglong2 s0, s1;
            s0.x = dup2(er0); s0.y = dup2(er1);
            s1.x = dup2(er2); s1.y = dup2(er3);
            *(ulonglong2*)&s_err2[lid * RPC]     = s0;
            *(ulonglong2*)&s_err2[lid * RPC + 2] = s1;
        }
        __syncthreads();

        // ---------- Phase D partial: err@Wo over this half's o range ----------
        {
            u64 g[RPC];
#pragma unroll
            for (int r = 0; r < RPC; ++r) g[r] = 0ULL;
            const int bo2 = uppr * 64;
            float4 pa = woD[(bo2 + 0) * 256 + lid];
            float4 pb = woD[(bo2 + 1) * 256 + lid];
            float4 pc_ = woD[(bo2 + 2) * 256 + lid];
            float4 pd = woD[(bo2 + 3) * 256 + lid];
#pragma unroll 2
            for (int o2i = 0; o2i < 64; o2i += 2) {
                float4 c0 = pa, c1 = pb;
                pa = pc_; pb = pd;
                int nx = o2i + 4; nx = (nx > 62) ? 60 : nx;
                pc_ = woD[(bo2 + nx)     * 256 + lid];
                pd  = woD[(bo2 + nx + 1) * 256 + lid];
                {
                    const int o = (bo2 + o2i) * 2;
                    ulonglong2 ea = *(const ulonglong2*)&s_err2[o * RPC];
                    ulonglong2 eb = *(const ulonglong2*)&s_err2[o * RPC + 2];
                    ulonglong2 ec = *(const ulonglong2*)&s_err2[o * RPC + 4];
                    ulonglong2 ed = *(const ulonglong2*)&s_err2[o * RPC + 6];
                    u64 wlo = pack2(c0.x, c0.y), whi = pack2(c0.z, c0.w);
                    fma2(g[0], ea.x, wlo);
                    fma2(g[1], ea.y, wlo);
                    fma2(g[2], eb.x, wlo);
                    fma2(g[3], eb.y, wlo);
                    fma2(g[0], ec.x, whi);
                    fma2(g[1], ec.y, whi);
                    fma2(g[2], ed.x, whi);
                    fma2(g[3], ed.y, whi);
                }
                {
                    const int o = (bo2 + o2i + 1) * 2;
                    ulonglong2 ea = *(const ulonglong2*)&s_err2[o * RPC];
                    ulonglong2 eb = *(const ulonglong2*)&s_err2[o * RPC + 2];
                    ulonglong2 ec = *(const ulonglong2*)&s_err2[o * RPC + 4];
                    ulonglong2 ed = *(const ulonglong2*)&s_err2[o * RPC + 6];
                    u64 wlo = pack2(c1.x, c1.y), whi = pack2(c1.z, c1.w);
                    fma2(g[0], ea.x, wlo);
                    fma2(g[1], ea.y, wlo);
                    fma2(g[2], eb.x, wlo);
                    fma2(g[3], eb.y, wlo);
                    fma2(g[0], ec.x, whi);
                    fma2(g[1], ec.y, whi);
                    fma2(g[2], ed.x, whi);
                    fma2(g[3], ed.y, whi);
                }
            }
            if (uppr) {
#pragma unroll
                for (int r = 0; r < RPC; ++r) s_part[lid * 4 + r] = g[r];
            } else {
#pragma unroll
                for (int r = 0; r < RPC; ++r) acc[r] = g[r];
            }
        }
        __syncthreads();

        // ---------- Phase D finalize: h_post, th = tanh(h_post), eh ----------
        if (!uppr) {
            u64 ep[RPC];
#pragma unroll
            for (int r = 0; r < RPC; ++r) {
                float g0, g1, p0, p1;
                unpack2(acc[r], g0, g1);
                unpack2(s_part[lid * 4 + r], p0, p1);
                g0 += p0; g1 += p1;
                float d0 = ALPHA_X * (1.0f - tp0[r] * tp0[r]) * g0;
                float d1 = ALPHA_X * (1.0f - tp1[r] * tp1[r]) * g1;
                h0[r] = hp0[r] - d0;
                h1[r] = hp1[r] - d1;
                ep[r] = pack2(d0, d1);
                s_th2[(j0)     * RPC + r] = dup2(tanhf(h0[r]));
                s_th2[(j0 + 1) * RPC + r] = dup2(tanhf(h1[r]));
            }
            ulonglong2 ev0, ev1;
            ev0.x = ep[0]; ev0.y = ep[1]; ev1.x = ep[2]; ev1.y = ep[3];
            *(ulonglong2*)&s_eh2[lid * RPC]     = ev0;
            *(ulonglong2*)&s_eh2[lid * RPC + 2] = ev1;
        }
        __syncthreads();

        // ---------- Phase E partial: eh@Wc over this half's j range ----------
        {
            u64 ce[4];
#pragma unroll
            for (int q = 0; q < 4; ++q) ce[q] = 0ULL;
            const int bj2 = uppr * 128;
            u64 p0[4], p1[4];
#pragma unroll
            for (int q = 0; q < 4; ++q) p0[q] = wcE[(bj2 + q) * 64 + cm];
#pragma unroll
            for (int q = 0; q < 4; ++q) p1[q] = wcE[(bj2 + 4 + q) * 64 + cm];
#pragma unroll 2
            for (int j2i = 0; j2i < 128; j2i += 4) {
                u64 cur[4];
#pragma unroll
                for (int q = 0; q < 4; ++q) { cur[q] = p0[q]; p0[q] = p1[q]; }
                int nx = j2i + 8; nx = (nx > 124) ? 120 : nx;
#pragma unroll
                for (int q = 0; q < 4; ++q) p1[q] = wcE[(bj2 + nx + q) * 64 + cm];
#pragma unroll
                for (int q = 0; q < 4; ++q)
                    fma2(ce[q], s_eh2[(bj2 + j2i + q) * RPC + cr], cur[q]);
            }
            u64 sA, sB, ca;
            add2(sA, ce[0], ce[1]);
            add2(sB, ce[2], ce[3]);
            add2(ca, sA, sB);
            if (uppr) s_part[lid] = ca;
            else      acc[0] = ca;
        }
        __syncthreads();

        // ---------- Phase E finalize: c update ----------
        if (!uppr) {
            float cl, ch, pl, ph;
            unpack2(acc[0], cl, ch);
            unpack2(s_part[lid], pl, ph);
            creg = creg - ALPHA_H * (cl + ch + pl + ph);
            s_c2[cm * RPC + cr] = dup2(creg);
        }
        __syncthreads();
    }
}

extern "C" void kernel_launch(void* const* d_in, const int* in_sizes, int n_in,
                              void* d_out, int out_size) {
    const float* x      = (const float*)d_in[0];
    const float* c_init = (const float*)d_in[1];
    const float* h_init = (const float*)d_in[2];
    const float* w_o    = (const float*)d_in[3];
    const float* b_o    = (const float*)d_in[4];
    const float* w_c    = (const float*)d_in[5];
    const float* w_r    = (const float*)d_in[6];
    const float* b_r    = (const float*)d_in[7];
    float* out          = (float*)d_out;

    pack_wrB<<<1024, 256>>>(w_r);
    pack_wcB<<<128,  256>>>(w_c);
    pack_woC<<<512,  256>>>(w_o);
    pack_woD<<<512,  256>>>(w_o);
    pack_wcE<<<128,  256>>>(w_c);

    pc_rnn_kernel<<<NCTA, NT>>>(x, c_init, h_init, b_o, b_r, out);
}

// round 9
// speedup vs baseline: 1.0716x; 1.0716x over previous
#include <cuda_runtime.h>
#include <cuda_bf16.h>

#define SEQ_LEN 512
#define BATCH   256
#define CAUSES  64
#define STATES  512
#define OUT_DIM 256
#define RPC     4
#define NCTA    (BATCH / RPC)
#define NT      1024
#define QT      256        // threads per quarter

#define ALPHA_X 0.1f
#define ALPHA_H 0.1f

typedef unsigned long long u64;

// ---------------- packed weight scratch (device globals: allocation-free) ----
__device__ float g_wrP[STATES/2 * STATES * 2];            // 262144
__device__ float g_wcB[CAUSES/2 * STATES * 2];            // 32768
__device__ float g_woC[STATES/4 * OUT_DIM * 4];           // 131072
__device__ float g_woD[OUT_DIM/2 * STATES * 2];           // 131072
__device__ float g_wcE[STATES/2 * CAUSES * 2];            // 32768

// ---------------- packed f32x2 helpers (PTX; ptxas won't auto-fuse) ----
__device__ __forceinline__ u64 dup2(float s) {
    u64 r; asm("mov.b64 %0, {%1, %1};" : "=l"(r) : "f"(s)); return r;
}
__device__ __forceinline__ u64 pack2(float a, float b) {
    u64 r; asm("mov.b64 %0, {%1, %2};" : "=l"(r) : "f"(a), "f"(b)); return r;
}
__device__ __forceinline__ void fma2(u64& d, u64 a, u64 b) {
    asm("fma.rn.f32x2 %0, %1, %2, %3;" : "=l"(d) : "l"(a), "l"(b), "l"(d));
}
__device__ __forceinline__ void add2(u64& d, u64 a, u64 b) {
    asm("add.rn.f32x2 %0, %1, %2;" : "=l"(d) : "l"(a), "l"(b));
}
__device__ __forceinline__ void unpack2(u64 v, float& lo, float& hi) {
    asm("mov.b64 {%0, %1}, %2;" : "=f"(lo), "=f"(hi) : "l"(v));
}

// ---------------- prologue pack kernels ----------
__global__ void pack_wrB(const float* __restrict__ w) {        // w_r [512][512]
    int idx = blockIdx.x * 256 + threadIdx.x;
    int k2 = idx >> 10, rem = idx & 1023;
    int jp = rem >> 2, c = rem & 3;
    int j = jp * 2 + (c & 1), k = k2 * 2 + (c >> 1);
    g_wrP[idx] = w[j * STATES + k];
}
__global__ void pack_wcB(const float* __restrict__ w) {        // w_c [512][64]
    int idx = blockIdx.x * 256 + threadIdx.x;
    int m2 = idx >> 10, rem = idx & 1023;
    int jp = rem >> 2, c = rem & 3;
    int j = jp * 2 + (c & 1), m = m2 * 2 + (c >> 1);
    g_wcB[idx] = w[j * CAUSES + m];
}
__global__ void pack_woC(const float* __restrict__ w) {        // w_o [256][512]
    int idx = blockIdx.x * 256 + threadIdx.x;
    int j4 = idx >> 10, rem = idx & 1023;
    int o = rem >> 2, jj = rem & 3;
    g_woC[idx] = w[o * STATES + j4 * 4 + jj];
}
__global__ void pack_woD(const float* __restrict__ w) {        // w_o [256][512]
    int idx = blockIdx.x * 256 + threadIdx.x;
    int o2 = idx >> 10, rem = idx & 1023;
    int jp = rem >> 2, c = rem & 3;
    int j = jp * 2 + (c & 1), o = o2 * 2 + (c >> 1);
    g_woD[idx] = w[o * STATES + j];
}
__global__ void pack_wcE(const float* __restrict__ w) {        // w_c [512][64]
    int idx = blockIdx.x * 256 + threadIdx.x;
    int j2 = idx >> 7, rem = idx & 127;
    int m = rem >> 1, jj = rem & 1;
    g_wcE[idx] = w[(j2 * 2 + jj) * CAUSES + m];
}

// ---- dynamic smem layout (u64 units) ----
#define OFF_TH    0                   // [512][4] tanh(h_post) dup'd          2048
#define OFF_TP    2048                // [512][2] tanh(h_prior) row-pairs     1024
#define OFF_ERR   3072                // [256][4] error dup'd                 1024
#define OFF_EH    4096                // [256][4] error_h j-pairs             1024
#define OFF_C     5120                // [64][4]  c dup'd                      256
#define OFF_HP    5376                // [256][4] h_prior packed (hp0,hp1)    1024
#define OFF_PART  6400                // [3][256][4] partials                 3072
#define SMEM_U64  9472
#define SMEM_BYTES (SMEM_U64 * 8)

// ---------------- main persistent recurrence kernel (4-way split-K, 32 warps) ----
__global__ __launch_bounds__(NT, 1)
void pc_rnn_kernel(const float* __restrict__ x,
                   const float* __restrict__ c_init,
                   const float* __restrict__ h_init,
                   const float* __restrict__ b_o,
                   const float* __restrict__ b_r,
                   float* __restrict__ out)
{
    extern __shared__ __align__(16) u64 S[];
    u64* s_th2  = S + OFF_TH;
    u64* s_tp2  = S + OFF_TP;
    u64* s_err2 = S + OFF_ERR;
    u64* s_eh2  = S + OFF_EH;
    u64* s_c2   = S + OFF_C;
    u64* s_hp   = S + OFF_HP;
    u64* s_part = S + OFF_PART;

    const int tid = threadIdx.x;
    const int lid = tid & (QT - 1);
    const int q   = tid >> 8;                 // quarter 0 = finalizer
    const int b0  = blockIdx.x * RPC;
    const int j0  = lid * 2;

    const float4* __restrict__ wrB = (const float4*)g_wrP;
    const float4* __restrict__ wcB = (const float4*)g_wcB;
    const float4* __restrict__ woC = (const float4*)g_woC;
    const float4* __restrict__ woD = (const float4*)g_woD;
    const u64*    __restrict__ wcE = (const u64*)g_wcE;

    float h0[RPC], h1[RPC];
    float rb0 = 0.f, rb1 = 0.f, rbo = 0.f, creg = 0.f;
    const int cm = lid & 63, cr = lid >> 6;

    if (q == 0) {
#pragma unroll
        for (int r = 0; r < RPC; ++r) {
            h0[r] = h_init[(size_t)(b0 + r) * STATES + j0];
            h1[r] = h_init[(size_t)(b0 + r) * STATES + j0 + 1];
            s_th2[(j0)     * RPC + r] = dup2(tanhf(h0[r]));
            s_th2[(j0 + 1) * RPC + r] = dup2(tanhf(h1[r]));
        }
        rb0 = b_r[j0]; rb1 = b_r[j0 + 1];
        rbo = b_o[lid];
        creg = c_init[(size_t)(b0 + cr) * CAUSES + cm];
        s_c2[cm * RPC + cr] = dup2(creg);
    }
    __syncthreads();

    for (int t = 0; t < SEQ_LEN; ++t) {
        // prefetch x_t (finalizer quarter; hidden behind phase B)
        float xr[RPC];
        if (q == 0) {
#pragma unroll
            for (int r = 0; r < RPC; ++r)
                xr[r] = x[((size_t)t * BATCH + b0 + r) * OUT_DIM + lid];
        }

        // ---------- Phase B partial: th@WrT + c@WcT over this quarter's k range ----------
        u64 acc[RPC];
#pragma unroll
        for (int r = 0; r < RPC; ++r) acc[r] = 0ULL;
        {
            const int bk2 = q * 64;
#pragma unroll 8
            for (int k2i = 0; k2i < 64; ++k2i) {
                const int k2 = bk2 + k2i;
                float4 w = wrB[k2 * 256 + lid];
                const int k = k2 * 2;
                ulonglong2 ta = *(const ulonglong2*)&s_th2[k * RPC];
                ulonglong2 tb = *(const ulonglong2*)&s_th2[k * RPC + 2];
                ulonglong2 tc = *(const ulonglong2*)&s_th2[k * RPC + 4];
                ulonglong2 td = *(const ulonglong2*)&s_th2[k * RPC + 6];
                u64 wlo = pack2(w.x, w.y), whi = pack2(w.z, w.w);
                fma2(acc[0], ta.x, wlo);
                fma2(acc[1], ta.y, wlo);
                fma2(acc[2], tb.x, wlo);
                fma2(acc[3], tb.y, wlo);
                fma2(acc[0], tc.x, whi);
                fma2(acc[1], tc.y, whi);
                fma2(acc[2], td.x, whi);
                fma2(acc[3], td.y, whi);
            }
            const int bm2 = q * 8;
#pragma unroll 8
            for (int m2i = 0; m2i < 8; ++m2i) {
                const int m2 = bm2 + m2i;
                float4 w = wcB[m2 * 256 + lid];
                const int m = m2 * 2;
                ulonglong2 ca_ = *(const ulonglong2*)&s_c2[m * RPC];
                ulonglong2 cb_ = *(const ulonglong2*)&s_c2[m * RPC + 2];
                ulonglong2 cc_ = *(const ulonglong2*)&s_c2[m * RPC + 4];
                ulonglong2 cd_ = *(const ulonglong2*)&s_c2[m * RPC + 6];
                u64 wlo = pack2(w.x, w.y), whi = pack2(w.z, w.w);
                fma2(acc[0], ca_.x, wlo);
                fma2(acc[1], ca_.y, wlo);
                fma2(acc[2], cb_.x, wlo);
                fma2(acc[3], cb_.y, wlo);
                fma2(acc[0], cc_.x, whi);
                fma2(acc[1], cc_.y, whi);
                fma2(acc[2], cd_.x, whi);
                fma2(acc[3], cd_.y, whi);
            }
        }
        if (q) {
#pragma unroll
            for (int r = 0; r < RPC; ++r) s_part[(q - 1) * 1024 + lid * 4 + r] = acc[r];
        }
        __syncthreads();

        // ---------- Phase B finalize: h_prior, tanh(h_prior) ----------
        if (q == 0) {
#pragma unroll
            for (int r = 0; r < RPC; ++r) {
                add2(acc[r], acc[r], s_part[lid * 4 + r]);
                add2(acc[r], acc[r], s_part[1024 + lid * 4 + r]);
                add2(acc[r], acc[r], s_part[2048 + lid * 4 + r]);
            }
            float tp0[RPC], tp1[RPC];
#pragma unroll
            for (int r = 0; r < RPC; ++r) {
                float a0, a1; unpack2(acc[r], a0, a1);
                float p0 = 0.9f * h0[r] + 0.1f * (a0 + rb0);
                float p1 = 0.9f * h1[r] + 0.1f * (a1 + rb1);
                s_hp[lid * 4 + r] = pack2(p0, p1);
                tp0[r] = tanhf(p0);
                tp1[r] = tanhf(p1);
            }
            ulonglong2 v0, v1;
            v0.x = pack2(tp0[0], tp0[1]); v0.y = pack2(tp0[2], tp0[3]);
            v1.x = pack2(tp1[0], tp1[1]); v1.y = pack2(tp1[2], tp1[3]);
            *(ulonglong2*)&s_tp2[j0 * 2]     = v0;
            *(ulonglong2*)&s_tp2[j0 * 2 + 2] = v1;
        }
        __syncthreads();

        // ---------- Phase C partial: tp@WoT over this quarter's j range (o = lid) ----------
        {
            u64 e01 = 0ULL, e23 = 0ULL;
            const int bj4 = q * 32;
#pragma unroll 8
            for (int j4i = 0; j4i < 32; ++j4i) {
                const int j4 = bj4 + j4i;
                float4 w = woC[j4 * 256 + lid];
                ulonglong2 p0 = *(const ulonglong2*)&s_tp2[(j4 * 4 + 0) * 2];
                ulonglong2 p1 = *(const ulonglong2*)&s_tp2[(j4 * 4 + 1) * 2];
                ulonglong2 p2 = *(const ulonglong2*)&s_tp2[(j4 * 4 + 2) * 2];
                ulonglong2 p3 = *(const ulonglong2*)&s_tp2[(j4 * 4 + 3) * 2];
                u64 w0 = dup2(w.x), w1 = dup2(w.y), w2 = dup2(w.z), w3 = dup2(w.w);
                fma2(e01, p0.x, w0); fma2(e23, p0.y, w0);
                fma2(e01, p1.x, w1); fma2(e23, p1.y, w1);
                fma2(e01, p2.x, w2); fma2(e23, p2.y, w2);
                fma2(e01, p3.x, w3); fma2(e23, p3.y, w3);
            }
            if (q) {
                s_part[(q - 1) * 1024 + lid * 4]     = e01;
                s_part[(q - 1) * 1024 + lid * 4 + 1] = e23;
            } else {
                acc[0] = e01; acc[1] = e23;
            }
        }
        __syncthreads();

        // ---------- Phase C finalize: err = pred - x_t; out + s_err2 ----------
        if (q == 0) {
            add2(acc[0], acc[0], s_part[lid * 4]);
            add2(acc[0], acc[0], s_part[1024 + lid * 4]);
            add2(acc[0], acc[0], s_part[2048 + lid * 4]);
            add2(acc[1], acc[1], s_part[lid * 4 + 1]);
            add2(acc[1], acc[1], s_part[1024 + lid * 4 + 1]);
            add2(acc[1], acc[1], s_part[2048 + lid * 4 + 1]);
            float q0, q1, q2, q3;
            unpack2(acc[0], q0, q1); unpack2(acc[1], q2, q3);
            float er0 = (q0 + rbo) - xr[0];
            float er1 = (q1 + rbo) - xr[1];
            float er2 = (q2 + rbo) - xr[2];
            float er3 = (q3 + rbo) - xr[3];
            size_t ob = ((size_t)t * BATCH + b0) * OUT_DIM + lid;
            out[ob]               = er0;
            out[ob + OUT_DIM]     = er1;
            out[ob + 2 * OUT_DIM] = er2;
            out[ob + 3 * OUT_DIM] = er3;
            ulonglong2 s0, s1;
            s0.x = dup2(er0); s0.y = dup2(er1);
            s1.x = dup2(er2); s1.y = dup2(er3);
            *(ulonglong2*)&s_err2[lid * RPC]     = s0;
            *(ulonglong2*)&s_err2[lid * RPC + 2] = s1;
        }
        __syncthreads();

        // ---------- Phase D partial: err@Wo over this quarter's o range ----------
        {
            u64 g[RPC];
#pragma unroll
            for (int r = 0; r < RPC; ++r) g[r] = 0ULL;
            const int bo2 = q * 32;
#pragma unroll 8
            for (int o2i = 0; o2i < 32; ++o2i) {
                const int o2 = bo2 + o2i;
                float4 w = woD[o2 * 256 + lid];
                const int o = o2 * 2;
                ulonglong2 ea = *(const ulonglong2*)&s_err2[o * RPC];
                ulonglong2 eb = *(const ulonglong2*)&s_err2[o * RPC + 2];
                ulonglong2 ec = *(const ulonglong2*)&s_err2[o * RPC + 4];
                ulonglong2 ed = *(const ulonglong2*)&s_err2[o * RPC + 6];
                u64 wlo = pack2(w.x, w.y), whi = pack2(w.z, w.w);
                fma2(g[0], ea.x, wlo);
                fma2(g[1], ea.y, wlo);
                fma2(g[2], eb.x, wlo);
                fma2(g[3], eb.y, wlo);
                fma2(g[0], ec.x, whi);
                fma2(g[1], ec.y, whi);
                fma2(g[2], ed.x, whi);
                fma2(g[3], ed.y, whi);
            }
            if (q) {
#pragma unroll
                for (int r = 0; r < RPC; ++r) s_part[(q - 1) * 1024 + lid * 4 + r] = g[r];
            } else {
#pragma unroll
                for (int r = 0; r < RPC; ++r) acc[r] = g[r];
            }
        }
        __syncthreads();

        // ---------- Phase D finalize: h_post, th = tanh(h_post), eh ----------
        if (q == 0) {
            u64 ep[RPC];
#pragma unroll
            for (int r = 0; r < RPC; ++r) {
                add2(acc[r], acc[r], s_part[lid * 4 + r]);
                add2(acc[r], acc[r], s_part[1024 + lid * 4 + r]);
                add2(acc[r], acc[r], s_part[2048 + lid * 4 + r]);
                float g0, g1; unpack2(acc[r], g0, g1);
                // reload tp for this (j-pair, r) and hp
                float t0a, t1a;
                {
                    u64 tpa = s_tp2[j0 * 2 + (r >> 1)];          // {tp0[2rp],tp0[2rp+1]}
                    u64 tpb = s_tp2[(j0 + 1) * 2 + (r >> 1)];
                    float x0, x1, y0, y1;
                    unpack2(tpa, x0, x1); unpack2(tpb, y0, y1);
                    t0a = (r & 1) ? x1 : x0;
                    t1a = (r & 1) ? y1 : y0;
                }
                float p0, p1; unpack2(s_hp[lid * 4 + r], p0, p1);
                float d0 = ALPHA_X * (1.0f - t0a * t0a) * g0;
                float d1 = ALPHA_X * (1.0f - t1a * t1a) * g1;
                h0[r] = p0 - d0;
                h1[r] = p1 - d1;
                ep[r] = pack2(d0, d1);
                s_th2[(j0)     * RPC + r] = dup2(tanhf(h0[r]));
                s_th2[(j0 + 1) * RPC + r] = dup2(tanhf(h1[r]));
            }
            ulonglong2 ev0, ev1;
            ev0.x = ep[0]; ev0.y = ep[1]; ev1.x = ep[2]; ev1.y = ep[3];
            *(ulonglong2*)&s_eh2[lid * RPC]     = ev0;
            *(ulonglong2*)&s_eh2[lid * RPC + 2] = ev1;
        }
        __syncthreads();

        // ---------- Phase E partial: eh@Wc over this quarter's j range ----------
        {
            u64 ce0 = 0ULL, ce1 = 0ULL;
            const int bj2 = q * 64;
#pragma unroll 8
            for (int j2i = 0; j2i < 64; j2i += 2) {
                const int j2 = bj2 + j2i;
                fma2(ce0, s_eh2[j2 * RPC + cr],       wcE[j2 * 64 + cm]);
                fma2(ce1, s_eh2[(j2 + 1) * RPC + cr], wcE[(j2 + 1) * 64 + cm]);
            }
            u64 ca;
            add2(ca, ce0, ce1);
            if (q) s_part[(q - 1) * 1024 + lid] = ca;
            else   acc[0] = ca;
        }
        __syncthreads();

        // ---------- Phase E finalize: c update ----------
        if (q == 0) {
            add2(acc[0], acc[0], s_part[lid]);
            add2(acc[0], acc[0], s_part[1024 + lid]);
            add2(acc[0], acc[0], s_part[2048 + lid]);
            float cl, ch;
            unpack2(acc[0], cl, ch);
            creg = creg - ALPHA_H * (cl + ch);
            s_c2[cm * RPC + cr] = dup2(creg);
        }
        __syncthreads();
    }
}

extern "C" void kernel_launch(void* const* d_in, const int* in_sizes, int n_in,
                              void* d_out, int out_size) {
    const float* x      = (const float*)d_in[0];
    const float* c_init = (const float*)d_in[1];
    const float* h_init = (const float*)d_in[2];
    const float* w_o    = (const float*)d_in[3];
    const float* b_o    = (const float*)d_in[4];
    const float* w_c    = (const float*)d_in[5];
    const float* w_r    = (const float*)d_in[6];
    const float* b_r    = (const float*)d_in[7];
    float* out          = (float*)d_out;

    pack_wrB<<<1024, 256>>>(w_r);
    pack_wcB<<<128,  256>>>(w_c);
    pack_woC<<<512,  256>>>(w_o);
    pack_woD<<<512,  256>>>(w_o);
    pack_wcE<<<128,  256>>>(w_c);

    cudaFuncSetAttribute(pc_rnn_kernel,
                         cudaFuncAttributeMaxDynamicSharedMemorySize, SMEM_BYTES);
    pc_rnn_kernel<<<NCTA, NT, SMEM_BYTES>>>(x, c_init, h_init, b_o, b_r, out);
}